// round 6
// baseline (speedup 1.0000x reference)
#include <cuda_runtime.h>
#include <cuda_fp16.h>
#include <cstdint>

// ---------------------------------------------------------------------------
// Swin shifted-window attention, R6: fused megakernel, 512 threads / 16 warps.
// CTA = 128 tokens = 2 windows; q/k/v/O resident in shared memory.
// ---------------------------------------------------------------------------

#define C       192
#define SHIFT   4
#define SCALE   0.17677669529663687f
#define ASTR    200   // smem row stride in halves (400B, LDSM conflict-free)

__device__ __half gw_qkv [576 * C];
__device__ __half gw_qkvb[576 * C];
__device__ __half gw_out [C * C];

__device__ __forceinline__ int tok_to_pix_row(int tok) {
    int bi  = tok >> 16;
    int rr  = tok & 65535;
    int win = rr >> 6, pix = rr & 63;
    int wy = win >> 5, wx = win & 31;
    int py = pix >> 3, px = pix & 7;
    int hh = (wy * 8 + py + SHIFT) & 255;
    int ww = (wx * 8 + px + SHIFT) & 255;
    return ((bi << 8 | hh) << 8 | ww) * C;
}

__device__ __forceinline__ uint32_t smem_u32(const void* p) {
    return (uint32_t)__cvta_generic_to_shared(p);
}
__device__ __forceinline__ void ldsm4(uint32_t& r0, uint32_t& r1, uint32_t& r2,
                                      uint32_t& r3, uint32_t a) {
    asm volatile("ldmatrix.sync.aligned.m8n8.x4.shared.b16 {%0,%1,%2,%3},[%4];\n"
                 : "=r"(r0), "=r"(r1), "=r"(r2), "=r"(r3) : "r"(a));
}
__device__ __forceinline__ void ldsm4t(uint32_t& r0, uint32_t& r1, uint32_t& r2,
                                       uint32_t& r3, uint32_t a) {
    asm volatile("ldmatrix.sync.aligned.m8n8.x4.trans.shared.b16 {%0,%1,%2,%3},[%4];\n"
                 : "=r"(r0), "=r"(r1), "=r"(r2), "=r"(r3) : "r"(a));
}
__device__ __forceinline__ void mma16816(float* c, const uint32_t* a, const uint32_t* b) {
    asm volatile(
        "mma.sync.aligned.m16n8k16.row.col.f32.f16.f16.f32 "
        "{%0,%1,%2,%3},{%4,%5,%6,%7},{%8,%9},{%0,%1,%2,%3};\n"
        : "+f"(c[0]), "+f"(c[1]), "+f"(c[2]), "+f"(c[3])
        : "r"(a[0]), "r"(a[1]), "r"(a[2]), "r"(a[3]), "r"(b[0]), "r"(b[1]));
}

// ---------------------------------------------------------------------------
__global__ __launch_bounds__(256) void prep_kernel(
    const float* __restrict__ w_qkv, const float* __restrict__ w_qkv_b,
    const float* __restrict__ w_out)
{
    int i = blockIdx.x * 256 + threadIdx.x;
    if (i < 576 * C) {
        gw_qkv [i] = __float2half_rn(w_qkv[i]);
        gw_qkvb[i] = __float2half_rn(w_qkv_b[i]);
    }
    if (i < C * C) gw_out[i] = __float2half_rn(w_out[i]);
}

// ---------------------------------------------------------------------------
// fused helpers (512 threads)
// ---------------------------------------------------------------------------
__device__ __forceinline__ void stage_input(const float* __restrict__ src,
                                            __half* dst, int m0, int tid)
{
    #pragma unroll
    for (int t = 0; t < 6; ++t) {
        int i = tid + t * 512;          // 3072 tasks of 8 floats
        int row = i / 24, off = (i % 24) * 8;
        const float* p = src + tok_to_pix_row(m0 + row) + off;
        float4 f0 = *(const float4*)p;
        float4 f1 = *(const float4*)(p + 4);
        __half2 hh[4] = { __floats2half2_rn(f0.x, f0.y), __floats2half2_rn(f0.z, f0.w),
                          __floats2half2_rn(f1.x, f1.y), __floats2half2_rn(f1.z, f1.w) };
        *(uint4*)&dst[row * ASTR + off] = *(uint4*)hh;
    }
}

__device__ __forceinline__ void load_w(__half* dst, const __half* __restrict__ w, int tid)
{
    #pragma unroll
    for (int t = 0; t < 5; ++t) {
        int i = tid + t * 512;          // 2304 tasks (96 rows x 24 uint4)
        if (i < 2304) {
            int row = i / 24, off = (i % 24) * 8;
            *(uint4*)&dst[row * ASTR + off] = *(const uint4*)(w + (size_t)row * C + off);
        }
    }
}

// 128x96 GEMM over K=192: warp tile 16x48 (16 warps = 8m x 2n)
__device__ __forceinline__ void gemm_group(const __half* As, const __half* Bs,
                                           int lane, int wm, int wn, float acc[6][4])
{
    #pragma unroll
    for (int kk = 0; kk < 192; kk += 16) {
        uint32_t afr[4], bfr[6][2];
        {
            uint32_t aa = smem_u32(&As[(wm + (lane & 15)) * ASTR + kk + 8 * (lane >> 4)]);
            ldsm4(afr[0], afr[1], afr[2], afr[3], aa);
        }
        #pragma unroll
        for (int g = 0; g < 3; ++g) {
            int m = lane >> 3;
            uint32_t ba = smem_u32(&Bs[(wn + 16 * g + (lane & 7) + 8 * (m >> 1)) * ASTR
                                       + kk + 8 * (m & 1)]);
            ldsm4(bfr[2*g][0], bfr[2*g][1], bfr[2*g+1][0], bfr[2*g+1][1], ba);
        }
        #pragma unroll
        for (int nt = 0; nt < 6; ++nt)
            mma16816(acc[nt], afr, bfr[nt]);
    }
}

// epilogue -> smem (fp16 + bias). bias pre-offset: bias[col], col in [0,96)
__device__ __forceinline__ void epi_smem(__half* dst, int colbase,
                                         const float* __restrict__ bias,
                                         int lane, int wm, int wn, float acc[6][4])
{
    #pragma unroll
    for (int nt = 0; nt < 6; ++nt) {
        int col = wn + 8 * nt + 2 * (lane & 3);
        float b0 = bias[col], b1 = bias[col + 1];
        int cd = colbase + col;
        int r0 = wm + (lane >> 2);
        *(__half2*)&dst[r0 * ASTR + cd] =
            __floats2half2_rn(acc[nt][0] + b0, acc[nt][1] + b1);
        *(__half2*)&dst[(r0 + 8) * ASTR + cd] =
            __floats2half2_rn(acc[nt][2] + b0, acc[nt][3] + b1);
    }
}

// one warp: 16 query rows x 64 keys for one (window, head); O overwrites Q
__device__ __forceinline__ void attn_task(__half* Qs, const __half* Ks, const __half* Vs,
                                          const float* rl, int w64, int hc, int rt,
                                          bool maskY, bool maskX, int lane)
{
    const int rbase = w64 + 16 * rt;

    // ---- S = Q K^T : 16x64, k=32 ----
    float c[8][4] = {};
    #pragma unroll
    for (int kc = 0; kc < 32; kc += 16) {
        uint32_t qf[4], kf[8][2];
        uint32_t aa = smem_u32(&Qs[(rbase + (lane & 15)) * ASTR + hc + kc + 8 * (lane >> 4)]);
        ldsm4(qf[0], qf[1], qf[2], qf[3], aa);
        #pragma unroll
        for (int g = 0; g < 4; ++g) {
            int m = lane >> 3;
            uint32_t ba = smem_u32(&Ks[(w64 + 16 * g + (lane & 7) + 8 * (m >> 1)) * ASTR
                                       + hc + kc + 8 * (m & 1)]);
            ldsm4(kf[2*g][0], kf[2*g][1], kf[2*g+1][0], kf[2*g+1][1], ba);
        }
        #pragma unroll
        for (int nt = 0; nt < 8; ++nt) mma16816(c[nt], qf, kf[nt]);
    }

    // ---- scale + rel bias + mask ----
    const int r1 = 16 * rt + (lane >> 2), r2 = r1 + 8;
    const int r1y = r1 >> 3, r1x = r1 & 7, r2y = r2 >> 3, r2x = r2 & 7;
    const int qx0 = 2 * (lane & 3), qx1 = qx0 + 1;
    #pragma unroll
    for (int nt = 0; nt < 8; ++nt) {
        bool mY1 = maskY && ((r1y < 4) != (nt < 4));
        bool mY2 = maskY && ((r2y < 4) != (nt < 4));
        bool mX0 = maskX && ((r1x < 4) != (qx0 < 4));
        bool mX1 = maskX && ((r1x < 4) != (qx1 < 4));
        float v0 = c[nt][0] * SCALE + rl[(r1y - nt + 7) * 15 + (r1x - qx0 + 7)];
        float v1 = c[nt][1] * SCALE + rl[(r1y - nt + 7) * 15 + (r1x - qx1 + 7)];
        float v2 = c[nt][2] * SCALE + rl[(r2y - nt + 7) * 15 + (r2x - qx0 + 7)];
        float v3 = c[nt][3] * SCALE + rl[(r2y - nt + 7) * 15 + (r2x - qx1 + 7)];
        c[nt][0] = (mY1 || mX0) ? -1e30f : v0;
        c[nt][1] = (mY1 || mX1) ? -1e30f : v1;
        c[nt][2] = (mY2 || mX0) ? -1e30f : v2;
        c[nt][3] = (mY2 || mX1) ? -1e30f : v3;
    }

    // ---- softmax (quad reduction) ----
    float mx1 = -1e30f, mx2 = -1e30f;
    #pragma unroll
    for (int nt = 0; nt < 8; ++nt) {
        mx1 = fmaxf(mx1, fmaxf(c[nt][0], c[nt][1]));
        mx2 = fmaxf(mx2, fmaxf(c[nt][2], c[nt][3]));
    }
    mx1 = fmaxf(mx1, __shfl_xor_sync(0xffffffffu, mx1, 1));
    mx1 = fmaxf(mx1, __shfl_xor_sync(0xffffffffu, mx1, 2));
    mx2 = fmaxf(mx2, __shfl_xor_sync(0xffffffffu, mx2, 1));
    mx2 = fmaxf(mx2, __shfl_xor_sync(0xffffffffu, mx2, 2));
    float s1 = 0.f, s2 = 0.f;
    #pragma unroll
    for (int nt = 0; nt < 8; ++nt) {
        c[nt][0] = __expf(c[nt][0] - mx1); s1 += c[nt][0];
        c[nt][1] = __expf(c[nt][1] - mx1); s1 += c[nt][1];
        c[nt][2] = __expf(c[nt][2] - mx2); s2 += c[nt][2];
        c[nt][3] = __expf(c[nt][3] - mx2); s2 += c[nt][3];
    }
    s1 += __shfl_xor_sync(0xffffffffu, s1, 1);
    s1 += __shfl_xor_sync(0xffffffffu, s1, 2);
    s2 += __shfl_xor_sync(0xffffffffu, s2, 1);
    s2 += __shfl_xor_sync(0xffffffffu, s2, 2);
    const float i1 = 1.f / s1, i2 = 1.f / s2;

    // ---- P -> fp16 A-fragments ----
    uint32_t p[4][4];
    #pragma unroll
    for (int kt = 0; kt < 4; ++kt) {
        __half2 h0 = __floats2half2_rn(c[2*kt  ][0] * i1, c[2*kt  ][1] * i1);
        __half2 h1 = __floats2half2_rn(c[2*kt  ][2] * i2, c[2*kt  ][3] * i2);
        __half2 h2 = __floats2half2_rn(c[2*kt+1][0] * i1, c[2*kt+1][1] * i1);
        __half2 h3 = __floats2half2_rn(c[2*kt+1][2] * i2, c[2*kt+1][3] * i2);
        p[kt][0] = *(uint32_t*)&h0; p[kt][1] = *(uint32_t*)&h1;
        p[kt][2] = *(uint32_t*)&h2; p[kt][3] = *(uint32_t*)&h3;
    }

    // ---- O = P V : 16x32, k=64 ----
    float o[4][4] = {};
    #pragma unroll
    for (int kt = 0; kt < 4; ++kt) {
        uint32_t vf[4][2];
        #pragma unroll
        for (int g = 0; g < 2; ++g) {
            int m = lane >> 3;
            uint32_t va = smem_u32(&Vs[(w64 + 16 * kt + (lane & 7) + 8 * (m & 1)) * ASTR
                                       + hc + 16 * g + 8 * (m >> 1)]);
            ldsm4t(vf[2*g][0], vf[2*g][1], vf[2*g+1][0], vf[2*g+1][1], va);
        }
        #pragma unroll
        for (int nt = 0; nt < 4; ++nt) mma16816(o[nt], p[kt], vf[nt]);
    }

    // ---- O overwrites Q (exclusive region per task) ----
    int gr1 = w64 + r1, gr2 = w64 + r2;
    #pragma unroll
    for (int nt = 0; nt < 4; ++nt) {
        int cc = hc + 8 * nt + 2 * (lane & 3);
        *(__half2*)&Qs[gr1 * ASTR + cc] = __floats2half2_rn(o[nt][0], o[nt][1]);
        *(__half2*)&Qs[gr2 * ASTR + cc] = __floats2half2_rn(o[nt][2], o[nt][3]);
    }
}

// ---------------------------------------------------------------------------
// The fused kernel. grid(1024), 512 threads.
// ---------------------------------------------------------------------------
#define SM_Q 0
#define SM_K 25600
#define SM_V 51200
#define SM_B 76800
#define SM_R 96000
#define FUSED_SMEM (96000 * 2 + 5400)

__global__ __launch_bounds__(512, 1)
void fused_kernel(const float* __restrict__ xin, const float* __restrict__ bin,
                  const float* __restrict__ b_qkv, const float* __restrict__ b_qkv_b,
                  const float* __restrict__ rel, const float* __restrict__ b_out,
                  float* __restrict__ out)
{
    extern __shared__ __half sm[];
    __half* Qs  = sm + SM_Q;
    __half* Ks  = sm + SM_K;
    __half* Vs  = sm + SM_V;
    __half* Bsm = sm + SM_B;
    float*  rel_s = (float*)(sm + SM_R);

    const int tid = threadIdx.x, warp = tid >> 5, lane = tid & 31;
    const int m0 = blockIdx.x * 128;
    const int wm = (warp >> 1) * 16, wn = (warp & 1) * 48;

    for (int i = tid; i < 1350; i += 512) rel_s[i] = rel[i];

    // ---- stage x, compute K and V ----
    stage_input(xin, Qs, m0, tid);
    __syncthreads();

    #pragma unroll
    for (int r = 0; r < 2; ++r) {
        __half* Dst = r ? Vs : Ks;
        #pragma unroll
        for (int g = 0; g < 2; ++g) {
            load_w(Bsm, gw_qkv + (size_t)(192 + r * 192 + g * 96) * C, tid);
            __syncthreads();
            float acc[6][4] = {};
            gemm_group(Qs, Bsm, lane, wm, wn, acc);
            epi_smem(Dst, g * 96, b_qkv + 192 + r * 192 + g * 96, lane, wm, wn, acc);
            __syncthreads();
        }
    }

    // ---- stage b, compute Q (both groups in registers, in-place store) ----
    stage_input(bin, Qs, m0, tid);
    __syncthreads();
    {
        float accA[6][4] = {}, accB[6][4] = {};
        load_w(Bsm, gw_qkvb, tid);
        __syncthreads();
        gemm_group(Qs, Bsm, lane, wm, wn, accA);
        __syncthreads();
        load_w(Bsm, gw_qkvb + (size_t)96 * C, tid);
        __syncthreads();
        gemm_group(Qs, Bsm, lane, wm, wn, accB);
        __syncthreads();                       // all Qs reads complete
        epi_smem(Qs, 0,  b_qkv_b,      lane, wm, wn, accA);
        epi_smem(Qs, 96, b_qkv_b + 96, lane, wm, wn, accB);
    }
    __syncthreads();

    // ---- attention: 48 tasks (2 win x 6 heads x 4 row-tiles), 16 warps ----
    {
        const int gw0 = blockIdx.x * 2;
        #pragma unroll
        for (int task = warp; task < 48; task += 16) {
            int pair = task >> 2, rt = task & 3;
            int win  = (pair >= 6) ? 1 : 0;
            int head = pair - win * 6;
            int wimg = (gw0 + win) & 1023;
            attn_task(Qs, Ks, Vs, rel_s + head * 225, win * 64, head * 32, rt,
                      (wimg >> 5) == 31, (wimg & 31) == 31, lane);
        }
    }
    __syncthreads();

    // ---- output projection + scatter ----
    int orow[2];
    {
        int r0 = m0 + wm + (lane >> 2);
        orow[0] = tok_to_pix_row(r0);
        orow[1] = tok_to_pix_row(r0 + 8);
    }
    #pragma unroll
    for (int g = 0; g < 2; ++g) {
        load_w(Bsm, gw_out + (size_t)g * 96 * C, tid);
        __syncthreads();
        float acc[6][4] = {};
        gemm_group(Qs, Bsm, lane, wm, wn, acc);
        #pragma unroll
        for (int nt = 0; nt < 6; ++nt) {
            int colg = g * 96 + wn + 8 * nt + 2 * (lane & 3);
            float b0 = b_out[colg], b1 = b_out[colg + 1];
            *(float2*)(out + orow[0] + colg) = make_float2(acc[nt][0] + b0, acc[nt][1] + b1);
            *(float2*)(out + orow[1] + colg) = make_float2(acc[nt][2] + b0, acc[nt][3] + b1);
        }
        __syncthreads();
    }
}

// ---------------------------------------------------------------------------
extern "C" void kernel_launch(void* const* d_in, const int* in_sizes, int n_in,
                              void* d_out, int out_size)
{
    const float* x        = (const float*)d_in[0];
    const float* b        = (const float*)d_in[1];
    const float* w_qkv    = (const float*)d_in[2];
    const float* b_qkv    = (const float*)d_in[3];
    const float* w_qkv_b  = (const float*)d_in[4];
    const float* b_qkv_b  = (const float*)d_in[5];
    const float* rel      = (const float*)d_in[6];
    const float* w_out    = (const float*)d_in[7];
    const float* b_out    = (const float*)d_in[8];
    float* out = (float*)d_out;

    cudaFuncSetAttribute(fused_kernel, cudaFuncAttributeMaxDynamicSharedMemorySize,
                         FUSED_SMEM);

    prep_kernel<<<432, 256>>>(w_qkv, w_qkv_b, w_out);
    fused_kernel<<<1024, 512, FUSED_SMEM>>>(x, b, b_qkv, b_qkv_b, rel, b_out, out);
}

// round 7
// speedup vs baseline: 1.1105x; 1.1105x over previous
#include <cuda_runtime.h>
#include <cuda_fp16.h>
#include <cstdint>

// ---------------------------------------------------------------------------
// Swin shifted-window attention, R7: fused megakernel, 256 threads / 8 warps,
// 32-row attention tasks (no spills), register-prefetched weight groups.
// ---------------------------------------------------------------------------

#define C       192
#define SHIFT   4
#define SCALE   0.17677669529663687f
#define ASTR    200   // smem row stride in halves (400B, LDSM conflict-free)

__device__ __half gw_qkv [576 * C];
__device__ __half gw_qkvb[576 * C];
__device__ __half gw_out [C * C];

__device__ __forceinline__ int tok_to_pix_row(int tok) {
    int bi  = tok >> 16;
    int rr  = tok & 65535;
    int win = rr >> 6, pix = rr & 63;
    int wy = win >> 5, wx = win & 31;
    int py = pix >> 3, px = pix & 7;
    int hh = (wy * 8 + py + SHIFT) & 255;
    int ww = (wx * 8 + px + SHIFT) & 255;
    return ((bi << 8 | hh) << 8 | ww) * C;
}

__device__ __forceinline__ uint32_t smem_u32(const void* p) {
    return (uint32_t)__cvta_generic_to_shared(p);
}
__device__ __forceinline__ void ldsm4(uint32_t& r0, uint32_t& r1, uint32_t& r2,
                                      uint32_t& r3, uint32_t a) {
    asm volatile("ldmatrix.sync.aligned.m8n8.x4.shared.b16 {%0,%1,%2,%3},[%4];\n"
                 : "=r"(r0), "=r"(r1), "=r"(r2), "=r"(r3) : "r"(a));
}
__device__ __forceinline__ void ldsm4t(uint32_t& r0, uint32_t& r1, uint32_t& r2,
                                       uint32_t& r3, uint32_t a) {
    asm volatile("ldmatrix.sync.aligned.m8n8.x4.trans.shared.b16 {%0,%1,%2,%3},[%4];\n"
                 : "=r"(r0), "=r"(r1), "=r"(r2), "=r"(r3) : "r"(a));
}
__device__ __forceinline__ void mma16816(float* c, const uint32_t* a, const uint32_t* b) {
    asm volatile(
        "mma.sync.aligned.m16n8k16.row.col.f32.f16.f16.f32 "
        "{%0,%1,%2,%3},{%4,%5,%6,%7},{%8,%9},{%0,%1,%2,%3};\n"
        : "+f"(c[0]), "+f"(c[1]), "+f"(c[2]), "+f"(c[3])
        : "r"(a[0]), "r"(a[1]), "r"(a[2]), "r"(a[3]), "r"(b[0]), "r"(b[1]));
}

// ---------------------------------------------------------------------------
__global__ __launch_bounds__(256) void prep_kernel(
    const float* __restrict__ w_qkv, const float* __restrict__ w_qkv_b,
    const float* __restrict__ w_out)
{
    int i = blockIdx.x * 256 + threadIdx.x;
    if (i < 576 * C) {
        gw_qkv [i] = __float2half_rn(w_qkv[i]);
        gw_qkvb[i] = __float2half_rn(w_qkv_b[i]);
    }
    if (i < C * C) gw_out[i] = __float2half_rn(w_out[i]);
}

// ---------------------------------------------------------------------------
// helpers (256 threads)
// ---------------------------------------------------------------------------
__device__ __forceinline__ void stage_input(const float* __restrict__ src,
                                            __half* dst, int m0, int tid)
{
    #pragma unroll
    for (int t = 0; t < 12; ++t) {
        int i = tid + t * 256;          // 3072 tasks of 8 floats
        int row = i / 24, off = (i % 24) * 8;
        const float* p = src + tok_to_pix_row(m0 + row) + off;
        float4 f0 = *(const float4*)p;
        float4 f1 = *(const float4*)(p + 4);
        __half2 hh[4] = { __floats2half2_rn(f0.x, f0.y), __floats2half2_rn(f0.z, f0.w),
                          __floats2half2_rn(f1.x, f1.y), __floats2half2_rn(f1.z, f1.w) };
        *(uint4*)&dst[row * ASTR + off] = *(uint4*)hh;
    }
}

// weight group prefetch: 96 rows x 192 halves = 2304 uint4, 9 per thread
__device__ __forceinline__ void pf_load(uint4 pf[9], const __half* __restrict__ w, int tid)
{
    #pragma unroll
    for (int t = 0; t < 9; ++t) {
        int i = tid + t * 256;
        int row = i / 24, off = (i % 24) * 8;
        pf[t] = *(const uint4*)(w + (size_t)row * C + off);
    }
}
__device__ __forceinline__ void pf_store(__half* dst, const uint4 pf[9], int tid)
{
    #pragma unroll
    for (int t = 0; t < 9; ++t) {
        int i = tid + t * 256;
        int row = i / 24, off = (i % 24) * 8;
        *(uint4*)&dst[row * ASTR + off] = pf[t];
    }
}

// 128x96 GEMM over K=192: warp tile 32x48 (8 warps = 4m x 2n)
__device__ __forceinline__ void gemm_group(const __half* As, const __half* Bs,
                                           int lane, int wm, int wn, float acc[2][6][4])
{
    #pragma unroll
    for (int kk = 0; kk < 192; kk += 16) {
        uint32_t afr[2][4], bfr[6][2];
        #pragma unroll
        for (int mt = 0; mt < 2; ++mt) {
            uint32_t aa = smem_u32(&As[(wm + 16 * mt + (lane & 15)) * ASTR
                                       + kk + 8 * (lane >> 4)]);
            ldsm4(afr[mt][0], afr[mt][1], afr[mt][2], afr[mt][3], aa);
        }
        #pragma unroll
        for (int g = 0; g < 3; ++g) {
            int m = lane >> 3;
            uint32_t ba = smem_u32(&Bs[(wn + 16 * g + (lane & 7) + 8 * (m >> 1)) * ASTR
                                       + kk + 8 * (m & 1)]);
            ldsm4(bfr[2*g][0], bfr[2*g][1], bfr[2*g+1][0], bfr[2*g+1][1], ba);
        }
        #pragma unroll
        for (int mt = 0; mt < 2; ++mt)
            #pragma unroll
            for (int nt = 0; nt < 6; ++nt)
                mma16816(acc[mt][nt], afr[mt], bfr[nt]);
    }
}

__device__ __forceinline__ void epi_smem(__half* dst, int colbase,
                                         const float* __restrict__ bias,
                                         int lane, int wm, int wn, float acc[2][6][4])
{
    #pragma unroll
    for (int nt = 0; nt < 6; ++nt) {
        int col = wn + 8 * nt + 2 * (lane & 3);
        float b0 = bias[col], b1 = bias[col + 1];
        int cd = colbase + col;
        #pragma unroll
        for (int mt = 0; mt < 2; ++mt) {
            int r0 = wm + 16 * mt + (lane >> 2);
            *(__half2*)&dst[r0 * ASTR + cd] =
                __floats2half2_rn(acc[mt][nt][0] + b0, acc[mt][nt][1] + b1);
            *(__half2*)&dst[(r0 + 8) * ASTR + cd] =
                __floats2half2_rn(acc[mt][nt][2] + b0, acc[mt][nt][3] + b1);
        }
    }
}

// one warp: 32 query rows x 64 keys for one (window, head); O overwrites Q
__device__ __forceinline__ void attn_task32(__half* Qs, const __half* Ks, const __half* Vs,
                                            const float* rl, int w64, int hc, int rt,
                                            bool maskY, bool maskX, int lane)
{
    const int rbase = w64 + 32 * rt;

    // ---- S = Q K^T : 32x64, k=32 ----
    float c[2][8][4] = {};
    #pragma unroll
    for (int kc = 0; kc < 32; kc += 16) {
        uint32_t qf[2][4], kf[8][2];
        #pragma unroll
        for (int mt = 0; mt < 2; ++mt) {
            uint32_t aa = smem_u32(&Qs[(rbase + 16 * mt + (lane & 15)) * ASTR
                                       + hc + kc + 8 * (lane >> 4)]);
            ldsm4(qf[mt][0], qf[mt][1], qf[mt][2], qf[mt][3], aa);
        }
        #pragma unroll
        for (int g = 0; g < 4; ++g) {
            int m = lane >> 3;
            uint32_t ba = smem_u32(&Ks[(w64 + 16 * g + (lane & 7) + 8 * (m >> 1)) * ASTR
                                       + hc + kc + 8 * (m & 1)]);
            ldsm4(kf[2*g][0], kf[2*g][1], kf[2*g+1][0], kf[2*g+1][1], ba);
        }
        #pragma unroll
        for (int mt = 0; mt < 2; ++mt)
            #pragma unroll
            for (int nt = 0; nt < 8; ++nt)
                mma16816(c[mt][nt], qf[mt], kf[nt]);
    }

    // ---- scale + rel bias + mask + softmax (per m-tile) ----
    const int qx0 = 2 * (lane & 3), qx1 = qx0 + 1;
    float i1[2], i2[2];
    #pragma unroll
    for (int mt = 0; mt < 2; ++mt) {
        int r1 = 32 * rt + 16 * mt + (lane >> 2), r2 = r1 + 8;
        int r1y = r1 >> 3, r1x = r1 & 7, r2y = r2 >> 3;   // r2x == r1x
        #pragma unroll
        for (int nt = 0; nt < 8; ++nt) {
            bool mY1 = maskY && ((r1y < 4) != (nt < 4));
            bool mY2 = maskY && ((r2y < 4) != (nt < 4));
            bool mX0 = maskX && ((r1x < 4) != (qx0 < 4));
            bool mX1 = maskX && ((r1x < 4) != (qx1 < 4));
            float v0 = c[mt][nt][0] * SCALE + rl[(r1y - nt + 7) * 15 + (r1x - qx0 + 7)];
            float v1 = c[mt][nt][1] * SCALE + rl[(r1y - nt + 7) * 15 + (r1x - qx1 + 7)];
            float v2 = c[mt][nt][2] * SCALE + rl[(r2y - nt + 7) * 15 + (r1x - qx0 + 7)];
            float v3 = c[mt][nt][3] * SCALE + rl[(r2y - nt + 7) * 15 + (r1x - qx1 + 7)];
            c[mt][nt][0] = (mY1 || mX0) ? -1e30f : v0;
            c[mt][nt][1] = (mY1 || mX1) ? -1e30f : v1;
            c[mt][nt][2] = (mY2 || mX0) ? -1e30f : v2;
            c[mt][nt][3] = (mY2 || mX1) ? -1e30f : v3;
        }
        float mx1 = -1e30f, mx2 = -1e30f;
        #pragma unroll
        for (int nt = 0; nt < 8; ++nt) {
            mx1 = fmaxf(mx1, fmaxf(c[mt][nt][0], c[mt][nt][1]));
            mx2 = fmaxf(mx2, fmaxf(c[mt][nt][2], c[mt][nt][3]));
        }
        mx1 = fmaxf(mx1, __shfl_xor_sync(0xffffffffu, mx1, 1));
        mx1 = fmaxf(mx1, __shfl_xor_sync(0xffffffffu, mx1, 2));
        mx2 = fmaxf(mx2, __shfl_xor_sync(0xffffffffu, mx2, 1));
        mx2 = fmaxf(mx2, __shfl_xor_sync(0xffffffffu, mx2, 2));
        float s1 = 0.f, s2 = 0.f;
        #pragma unroll
        for (int nt = 0; nt < 8; ++nt) {
            c[mt][nt][0] = __expf(c[mt][nt][0] - mx1); s1 += c[mt][nt][0];
            c[mt][nt][1] = __expf(c[mt][nt][1] - mx1); s1 += c[mt][nt][1];
            c[mt][nt][2] = __expf(c[mt][nt][2] - mx2); s2 += c[mt][nt][2];
            c[mt][nt][3] = __expf(c[mt][nt][3] - mx2); s2 += c[mt][nt][3];
        }
        s1 += __shfl_xor_sync(0xffffffffu, s1, 1);
        s1 += __shfl_xor_sync(0xffffffffu, s1, 2);
        s2 += __shfl_xor_sync(0xffffffffu, s2, 1);
        s2 += __shfl_xor_sync(0xffffffffu, s2, 2);
        i1[mt] = 1.f / s1; i2[mt] = 1.f / s2;
    }

    // ---- P -> fp16 A-fragments ----
    uint32_t p[2][4][4];
    #pragma unroll
    for (int mt = 0; mt < 2; ++mt)
        #pragma unroll
        for (int kt = 0; kt < 4; ++kt) {
            __half2 h0 = __floats2half2_rn(c[mt][2*kt  ][0] * i1[mt], c[mt][2*kt  ][1] * i1[mt]);
            __half2 h1 = __floats2half2_rn(c[mt][2*kt  ][2] * i2[mt], c[mt][2*kt  ][3] * i2[mt]);
            __half2 h2 = __floats2half2_rn(c[mt][2*kt+1][0] * i1[mt], c[mt][2*kt+1][1] * i1[mt]);
            __half2 h3 = __floats2half2_rn(c[mt][2*kt+1][2] * i2[mt], c[mt][2*kt+1][3] * i2[mt]);
            p[mt][kt][0] = *(uint32_t*)&h0; p[mt][kt][1] = *(uint32_t*)&h1;
            p[mt][kt][2] = *(uint32_t*)&h2; p[mt][kt][3] = *(uint32_t*)&h3;
        }

    // ---- O = P V : 32x32, k=64 (V fragments shared across m-tiles) ----
    float o[2][4][4] = {};
    #pragma unroll
    for (int kt = 0; kt < 4; ++kt) {
        uint32_t vf[4][2];
        #pragma unroll
        for (int g = 0; g < 2; ++g) {
            int m = lane >> 3;
            uint32_t va = smem_u32(&Vs[(w64 + 16 * kt + (lane & 7) + 8 * (m & 1)) * ASTR
                                       + hc + 16 * g + 8 * (m >> 1)]);
            ldsm4t(vf[2*g][0], vf[2*g][1], vf[2*g+1][0], vf[2*g+1][1], va);
        }
        #pragma unroll
        for (int mt = 0; mt < 2; ++mt)
            #pragma unroll
            for (int nt = 0; nt < 4; ++nt)
                mma16816(o[mt][nt], p[mt][kt], vf[nt]);
    }

    // ---- O overwrites Q (exclusive region per task) ----
    #pragma unroll
    for (int mt = 0; mt < 2; ++mt) {
        int r1 = rbase + 16 * mt + (lane >> 2), r2 = r1 + 8;
        #pragma unroll
        for (int nt = 0; nt < 4; ++nt) {
            int cc = hc + 8 * nt + 2 * (lane & 3);
            *(__half2*)&Qs[r1 * ASTR + cc] = __floats2half2_rn(o[mt][nt][0], o[mt][nt][1]);
            *(__half2*)&Qs[r2 * ASTR + cc] = __floats2half2_rn(o[mt][nt][2], o[mt][nt][3]);
        }
    }
}

// ---------------------------------------------------------------------------
// The fused kernel. grid(1024), 256 threads.
// smem: Qs(128x200) Ks Vs Bs(96x200) rel(1350 f)
// ---------------------------------------------------------------------------
#define SM_Q 0
#define SM_K 25600
#define SM_V 51200
#define SM_B 76800
#define SM_R 96000
#define FUSED_SMEM (96000 * 2 + 5400)

__global__ __launch_bounds__(256, 1)
void fused_kernel(const float* __restrict__ xin, const float* __restrict__ bin,
                  const float* __restrict__ b_qkv, const float* __restrict__ b_qkv_b,
                  const float* __restrict__ rel, const float* __restrict__ b_out,
                  float* __restrict__ out)
{
    extern __shared__ __half sm[];
    __half* Qs  = sm + SM_Q;
    __half* Ks  = sm + SM_K;
    __half* Vs  = sm + SM_V;
    __half* Bsm = sm + SM_B;
    float*  rel_s = (float*)(sm + SM_R);

    const int tid = threadIdx.x, warp = tid >> 5, lane = tid & 31;
    const int m0 = blockIdx.x * 128;
    const int wm = (warp >> 1) * 32, wn = (warp & 1) * 48;

    const __half* Wptr[8] = {
        gw_qkv + (size_t)192 * C, gw_qkv + (size_t)288 * C,
        gw_qkv + (size_t)384 * C, gw_qkv + (size_t)480 * C,
        gw_qkvb, gw_qkvb + (size_t)96 * C,
        gw_out,  gw_out  + (size_t)96 * C };

    uint4 pf[9];

    for (int i = tid; i < 1350; i += 256) rel_s[i] = rel[i];

    // ---- stage x, prefetch first weights ----
    stage_input(xin, Qs, m0, tid);
    pf_load(pf, Wptr[0], tid);
    __syncthreads();

    // ---- K, V (4 groups) ----
    #pragma unroll
    for (int s = 0; s < 4; ++s) {
        pf_store(Bsm, pf, tid);
        __syncthreads();
        pf_load(pf, Wptr[s + 1], tid);          // overlaps gemm below
        float acc[2][6][4] = {};
        gemm_group(Qs, Bsm, lane, wm, wn, acc);
        epi_smem((s < 2) ? Ks : Vs, (s & 1) * 96,
                 b_qkv + 192 + s * 96, lane, wm, wn, acc);
        __syncthreads();
    }

    // ---- stage b, compute Q (both groups in regs, in-place store) ----
    stage_input(bin, Qs, m0, tid);
    __syncthreads();
    {
        float accA[2][6][4] = {}, accB[2][6][4] = {};
        pf_store(Bsm, pf, tid);                 // W4
        __syncthreads();
        pf_load(pf, Wptr[5], tid);
        gemm_group(Qs, Bsm, lane, wm, wn, accA);
        __syncthreads();
        pf_store(Bsm, pf, tid);                 // W5
        __syncthreads();
        pf_load(pf, Wptr[6], tid);
        gemm_group(Qs, Bsm, lane, wm, wn, accB);
        __syncthreads();                        // all Qs reads done
        epi_smem(Qs, 0,  b_qkv_b,      lane, wm, wn, accA);
        epi_smem(Qs, 96, b_qkv_b + 96, lane, wm, wn, accB);
    }
    __syncthreads();

    // ---- attention: 24 tasks (2 win x 6 heads x 2 row-halves), 8 warps ----
    {
        const int gw0 = blockIdx.x * 2;
        #pragma unroll
        for (int task = warp; task < 24; task += 8) {
            int pair = task >> 1, rt = task & 1;
            int win  = (pair >= 6) ? 1 : 0;
            int head = pair - win * 6;
            int wimg = (gw0 + win) & 1023;
            attn_task32(Qs, Ks, Vs, rel_s + head * 225, win * 64, head * 32, rt,
                        (wimg >> 5) == 31, (wimg & 31) == 31, lane);
        }
    }
    __syncthreads();

    // ---- output projection + scatter ----
    int orow[2][2];
    #pragma unroll
    for (int mt = 0; mt < 2; ++mt) {
        int r0 = m0 + wm + 16 * mt + (lane >> 2);
        orow[mt][0] = tok_to_pix_row(r0);
        orow[mt][1] = tok_to_pix_row(r0 + 8);
    }
    #pragma unroll
    for (int g = 0; g < 2; ++g) {
        pf_store(Bsm, pf, tid);                 // W6 / W7
        __syncthreads();
        if (g == 0) pf_load(pf, Wptr[7], tid);
        float acc[2][6][4] = {};
        gemm_group(Qs, Bsm, lane, wm, wn, acc);
        #pragma unroll
        for (int nt = 0; nt < 6; ++nt) {
            int colg = g * 96 + wn + 8 * nt + 2 * (lane & 3);
            float b0 = b_out[colg], b1 = b_out[colg + 1];
            #pragma unroll
            for (int mt = 0; mt < 2; ++mt) {
                *(float2*)(out + orow[mt][0] + colg) =
                    make_float2(acc[mt][nt][0] + b0, acc[mt][nt][1] + b1);
                *(float2*)(out + orow[mt][1] + colg) =
                    make_float2(acc[mt][nt][2] + b0, acc[mt][nt][3] + b1);
            }
        }
        __syncthreads();
    }
}

// ---------------------------------------------------------------------------
extern "C" void kernel_launch(void* const* d_in, const int* in_sizes, int n_in,
                              void* d_out, int out_size)
{
    const float* x        = (const float*)d_in[0];
    const float* b        = (const float*)d_in[1];
    const float* w_qkv    = (const float*)d_in[2];
    const float* b_qkv    = (const float*)d_in[3];
    const float* w_qkv_b  = (const float*)d_in[4];
    const float* b_qkv_b  = (const float*)d_in[5];
    const float* rel      = (const float*)d_in[6];
    const float* w_out    = (const float*)d_in[7];
    const float* b_out    = (const float*)d_in[8];
    float* out = (float*)d_out;

    cudaFuncSetAttribute(fused_kernel, cudaFuncAttributeMaxDynamicSharedMemorySize,
                         FUSED_SMEM);

    prep_kernel<<<432, 256>>>(w_qkv, w_qkv_b, w_out);
    fused_kernel<<<1024, 256, FUSED_SMEM>>>(x, b, b_qkv, b_qkv_b, rel, b_out, out);
}

// round 8
// speedup vs baseline: 1.1736x; 1.0568x over previous
#include <cuda_runtime.h>
#include <cuda_fp16.h>
#include <cstdint>

// ---------------------------------------------------------------------------
// Swin shifted-window attention, R8: fused megakernel, 384 threads / 12 warps,
// 32x32 GEMM warp tiles, fp16-parked q-phase (regs <= 170), 32-row attn tasks.
// ---------------------------------------------------------------------------

#define C       192
#define SHIFT   4
#define SCALE   0.17677669529663687f
#define ASTR    200   // smem row stride in halves (400B, LDSM conflict-free)

__device__ __half gw_qkv [576 * C];
__device__ __half gw_qkvb[576 * C];
__device__ __half gw_out [C * C];

__device__ __forceinline__ int tok_to_pix_row(int tok) {
    int bi  = tok >> 16;
    int rr  = tok & 65535;
    int win = rr >> 6, pix = rr & 63;
    int wy = win >> 5, wx = win & 31;
    int py = pix >> 3, px = pix & 7;
    int hh = (wy * 8 + py + SHIFT) & 255;
    int ww = (wx * 8 + px + SHIFT) & 255;
    return ((bi << 8 | hh) << 8 | ww) * C;
}

__device__ __forceinline__ uint32_t smem_u32(const void* p) {
    return (uint32_t)__cvta_generic_to_shared(p);
}
__device__ __forceinline__ void ldsm4(uint32_t& r0, uint32_t& r1, uint32_t& r2,
                                      uint32_t& r3, uint32_t a) {
    asm volatile("ldmatrix.sync.aligned.m8n8.x4.shared.b16 {%0,%1,%2,%3},[%4];\n"
                 : "=r"(r0), "=r"(r1), "=r"(r2), "=r"(r3) : "r"(a));
}
__device__ __forceinline__ void ldsm4t(uint32_t& r0, uint32_t& r1, uint32_t& r2,
                                       uint32_t& r3, uint32_t a) {
    asm volatile("ldmatrix.sync.aligned.m8n8.x4.trans.shared.b16 {%0,%1,%2,%3},[%4];\n"
                 : "=r"(r0), "=r"(r1), "=r"(r2), "=r"(r3) : "r"(a));
}
__device__ __forceinline__ void mma16816(float* c, const uint32_t* a, const uint32_t* b) {
    asm volatile(
        "mma.sync.aligned.m16n8k16.row.col.f32.f16.f16.f32 "
        "{%0,%1,%2,%3},{%4,%5,%6,%7},{%8,%9},{%0,%1,%2,%3};\n"
        : "+f"(c[0]), "+f"(c[1]), "+f"(c[2]), "+f"(c[3])
        : "r"(a[0]), "r"(a[1]), "r"(a[2]), "r"(a[3]), "r"(b[0]), "r"(b[1]));
}

// ---------------------------------------------------------------------------
__global__ __launch_bounds__(256) void prep_kernel(
    const float* __restrict__ w_qkv, const float* __restrict__ w_qkv_b,
    const float* __restrict__ w_out)
{
    int i = blockIdx.x * 256 + threadIdx.x;
    if (i < 576 * C) {
        gw_qkv [i] = __float2half_rn(w_qkv[i]);
        gw_qkvb[i] = __float2half_rn(w_qkv_b[i]);
    }
    if (i < C * C) gw_out[i] = __float2half_rn(w_out[i]);
}

// ---------------------------------------------------------------------------
// helpers (384 threads)
// ---------------------------------------------------------------------------
__device__ __forceinline__ void stage_input(const float* __restrict__ src,
                                            __half* dst, int m0, int tid)
{
    #pragma unroll
    for (int t = 0; t < 8; ++t) {
        int i = tid + t * 384;          // 3072 tasks of 8 floats
        int row = i / 24, off = (i % 24) * 8;
        const float* p = src + tok_to_pix_row(m0 + row) + off;
        float4 f0 = *(const float4*)p;
        float4 f1 = *(const float4*)(p + 4);
        __half2 hh[4] = { __floats2half2_rn(f0.x, f0.y), __floats2half2_rn(f0.z, f0.w),
                          __floats2half2_rn(f1.x, f1.y), __floats2half2_rn(f1.z, f1.w) };
        *(uint4*)&dst[row * ASTR + off] = *(uint4*)hh;
    }
}

// weight group prefetch: 96 rows x 192 halves = 2304 uint4, 6 per thread
__device__ __forceinline__ void pf_load(uint4 pf[6], const __half* __restrict__ w, int tid)
{
    #pragma unroll
    for (int t = 0; t < 6; ++t) {
        int i = tid + t * 384;
        int row = i / 24, off = (i % 24) * 8;
        pf[t] = *(const uint4*)(w + (size_t)row * C + off);
    }
}
__device__ __forceinline__ void pf_store(__half* dst, const uint4 pf[6], int tid)
{
    #pragma unroll
    for (int t = 0; t < 6; ++t) {
        int i = tid + t * 384;
        int row = i / 24, off = (i % 24) * 8;
        *(uint4*)&dst[row * ASTR + off] = pf[t];
    }
}

// 128x96 GEMM over K=192: warp tile 32x32 (12 warps = 4m x 3n)
__device__ __forceinline__ void gemm_group(const __half* As, const __half* Bs,
                                           int lane, int wm, int wn, float acc[2][4][4])
{
    #pragma unroll
    for (int kk = 0; kk < 192; kk += 16) {
        uint32_t afr[2][4], bfr[4][2];
        #pragma unroll
        for (int mt = 0; mt < 2; ++mt) {
            uint32_t aa = smem_u32(&As[(wm + 16 * mt + (lane & 15)) * ASTR
                                       + kk + 8 * (lane >> 4)]);
            ldsm4(afr[mt][0], afr[mt][1], afr[mt][2], afr[mt][3], aa);
        }
        #pragma unroll
        for (int g = 0; g < 2; ++g) {
            int m = lane >> 3;
            uint32_t ba = smem_u32(&Bs[(wn + 16 * g + (lane & 7) + 8 * (m >> 1)) * ASTR
                                       + kk + 8 * (m & 1)]);
            ldsm4(bfr[2*g][0], bfr[2*g][1], bfr[2*g+1][0], bfr[2*g+1][1], ba);
        }
        #pragma unroll
        for (int mt = 0; mt < 2; ++mt)
            #pragma unroll
            for (int nt = 0; nt < 4; ++nt)
                mma16816(acc[mt][nt], afr[mt], bfr[nt]);
    }
}

// epilogue straight to smem (no aliasing case): fp16 + bias
__device__ __forceinline__ void epi_smem(__half* dst, int colbase,
                                         const float* __restrict__ bias,
                                         int lane, int wm, int wn, float acc[2][4][4])
{
    #pragma unroll
    for (int nt = 0; nt < 4; ++nt) {
        int col = wn + 8 * nt + 2 * (lane & 3);
        float b0 = bias[col], b1 = bias[col + 1];
        int cd = colbase + col;
        #pragma unroll
        for (int mt = 0; mt < 2; ++mt) {
            int r0 = wm + 16 * mt + (lane >> 2);
            *(__half2*)&dst[r0 * ASTR + cd] =
                __floats2half2_rn(acc[mt][nt][0] + b0, acc[mt][nt][1] + b1);
            *(__half2*)&dst[(r0 + 8) * ASTR + cd] =
                __floats2half2_rn(acc[mt][nt][2] + b0, acc[mt][nt][3] + b1);
        }
    }
}

// park biased result as fp16 in registers (16 half2 per group)
__device__ __forceinline__ void epi_park(uint32_t park[16],
                                         const float* __restrict__ bias,
                                         int lane, int wn, float acc[2][4][4])
{
    #pragma unroll
    for (int nt = 0; nt < 4; ++nt) {
        int col = wn + 8 * nt + 2 * (lane & 3);
        float b0 = bias[col], b1 = bias[col + 1];
        #pragma unroll
        for (int mt = 0; mt < 2; ++mt) {
            __half2 h0 = __floats2half2_rn(acc[mt][nt][0] + b0, acc[mt][nt][1] + b1);
            __half2 h1 = __floats2half2_rn(acc[mt][nt][2] + b0, acc[mt][nt][3] + b1);
            park[nt * 4 + mt * 2 + 0] = *(uint32_t*)&h0;
            park[nt * 4 + mt * 2 + 1] = *(uint32_t*)&h1;
        }
    }
}
__device__ __forceinline__ void epi_unpark(__half* dst, int colbase,
                                           int lane, int wm, int wn,
                                           const uint32_t park[16])
{
    #pragma unroll
    for (int nt = 0; nt < 4; ++nt) {
        int cd = colbase + wn + 8 * nt + 2 * (lane & 3);
        #pragma unroll
        for (int mt = 0; mt < 2; ++mt) {
            int r0 = wm + 16 * mt + (lane >> 2);
            *(uint32_t*)&dst[r0 * ASTR + cd]       = park[nt * 4 + mt * 2 + 0];
            *(uint32_t*)&dst[(r0 + 8) * ASTR + cd] = park[nt * 4 + mt * 2 + 1];
        }
    }
}

// one warp: 32 query rows x 64 keys for one (window, head); O overwrites Q
__device__ __forceinline__ void attn_task32(__half* Qs, const __half* Ks, const __half* Vs,
                                            const float* rl, int w64, int hc, int rt,
                                            bool maskY, bool maskX, int lane)
{
    const int rbase = w64 + 32 * rt;

    // ---- S = Q K^T : 32x64, k=32 ----
    float c[2][8][4] = {};
    #pragma unroll
    for (int kc = 0; kc < 32; kc += 16) {
        uint32_t qf[2][4], kf[8][2];
        #pragma unroll
        for (int mt = 0; mt < 2; ++mt) {
            uint32_t aa = smem_u32(&Qs[(rbase + 16 * mt + (lane & 15)) * ASTR
                                       + hc + kc + 8 * (lane >> 4)]);
            ldsm4(qf[mt][0], qf[mt][1], qf[mt][2], qf[mt][3], aa);
        }
        #pragma unroll
        for (int g = 0; g < 4; ++g) {
            int m = lane >> 3;
            uint32_t ba = smem_u32(&Ks[(w64 + 16 * g + (lane & 7) + 8 * (m >> 1)) * ASTR
                                       + hc + kc + 8 * (m & 1)]);
            ldsm4(kf[2*g][0], kf[2*g][1], kf[2*g+1][0], kf[2*g+1][1], ba);
        }
        #pragma unroll
        for (int mt = 0; mt < 2; ++mt)
            #pragma unroll
            for (int nt = 0; nt < 8; ++nt)
                mma16816(c[mt][nt], qf[mt], kf[nt]);
    }

    // ---- scale + rel bias + mask + softmax (per m-tile) ----
    const int qx0 = 2 * (lane & 3), qx1 = qx0 + 1;
    float i1[2], i2[2];
    #pragma unroll
    for (int mt = 0; mt < 2; ++mt) {
        int r1 = 32 * rt + 16 * mt + (lane >> 2), r2 = r1 + 8;
        int r1y = r1 >> 3, r1x = r1 & 7, r2y = r2 >> 3;   // r2x == r1x
        #pragma unroll
        for (int nt = 0; nt < 8; ++nt) {
            bool mY1 = maskY && ((r1y < 4) != (nt < 4));
            bool mY2 = maskY && ((r2y < 4) != (nt < 4));
            bool mX0 = maskX && ((r1x < 4) != (qx0 < 4));
            bool mX1 = maskX && ((r1x < 4) != (qx1 < 4));
            float v0 = c[mt][nt][0] * SCALE + rl[(r1y - nt + 7) * 15 + (r1x - qx0 + 7)];
            float v1 = c[mt][nt][1] * SCALE + rl[(r1y - nt + 7) * 15 + (r1x - qx1 + 7)];
            float v2 = c[mt][nt][2] * SCALE + rl[(r2y - nt + 7) * 15 + (r1x - qx0 + 7)];
            float v3 = c[mt][nt][3] * SCALE + rl[(r2y - nt + 7) * 15 + (r1x - qx1 + 7)];
            c[mt][nt][0] = (mY1 || mX0) ? -1e30f : v0;
            c[mt][nt][1] = (mY1 || mX1) ? -1e30f : v1;
            c[mt][nt][2] = (mY2 || mX0) ? -1e30f : v2;
            c[mt][nt][3] = (mY2 || mX1) ? -1e30f : v3;
        }
        float mx1 = -1e30f, mx2 = -1e30f;
        #pragma unroll
        for (int nt = 0; nt < 8; ++nt) {
            mx1 = fmaxf(mx1, fmaxf(c[mt][nt][0], c[mt][nt][1]));
            mx2 = fmaxf(mx2, fmaxf(c[mt][nt][2], c[mt][nt][3]));
        }
        mx1 = fmaxf(mx1, __shfl_xor_sync(0xffffffffu, mx1, 1));
        mx1 = fmaxf(mx1, __shfl_xor_sync(0xffffffffu, mx1, 2));
        mx2 = fmaxf(mx2, __shfl_xor_sync(0xffffffffu, mx2, 1));
        mx2 = fmaxf(mx2, __shfl_xor_sync(0xffffffffu, mx2, 2));
        float s1 = 0.f, s2 = 0.f;
        #pragma unroll
        for (int nt = 0; nt < 8; ++nt) {
            c[mt][nt][0] = __expf(c[mt][nt][0] - mx1); s1 += c[mt][nt][0];
            c[mt][nt][1] = __expf(c[mt][nt][1] - mx1); s1 += c[mt][nt][1];
            c[mt][nt][2] = __expf(c[mt][nt][2] - mx2); s2 += c[mt][nt][2];
            c[mt][nt][3] = __expf(c[mt][nt][3] - mx2); s2 += c[mt][nt][3];
        }
        s1 += __shfl_xor_sync(0xffffffffu, s1, 1);
        s1 += __shfl_xor_sync(0xffffffffu, s1, 2);
        s2 += __shfl_xor_sync(0xffffffffu, s2, 1);
        s2 += __shfl_xor_sync(0xffffffffu, s2, 2);
        i1[mt] = 1.f / s1; i2[mt] = 1.f / s2;
    }

    // ---- P -> fp16 A-fragments ----
    uint32_t p[2][4][4];
    #pragma unroll
    for (int mt = 0; mt < 2; ++mt)
        #pragma unroll
        for (int kt = 0; kt < 4; ++kt) {
            __half2 h0 = __floats2half2_rn(c[mt][2*kt  ][0] * i1[mt], c[mt][2*kt  ][1] * i1[mt]);
            __half2 h1 = __floats2half2_rn(c[mt][2*kt  ][2] * i2[mt], c[mt][2*kt  ][3] * i2[mt]);
            __half2 h2 = __floats2half2_rn(c[mt][2*kt+1][0] * i1[mt], c[mt][2*kt+1][1] * i1[mt]);
            __half2 h3 = __floats2half2_rn(c[mt][2*kt+1][2] * i2[mt], c[mt][2*kt+1][3] * i2[mt]);
            p[mt][kt][0] = *(uint32_t*)&h0; p[mt][kt][1] = *(uint32_t*)&h1;
            p[mt][kt][2] = *(uint32_t*)&h2; p[mt][kt][3] = *(uint32_t*)&h3;
        }

    // ---- O = P V : 32x32, k=64 (V fragments shared across m-tiles) ----
    float o[2][4][4] = {};
    #pragma unroll
    for (int kt = 0; kt < 4; ++kt) {
        uint32_t vf[4][2];
        #pragma unroll
        for (int g = 0; g < 2; ++g) {
            int m = lane >> 3;
            uint32_t va = smem_u32(&Vs[(w64 + 16 * kt + (lane & 7) + 8 * (m & 1)) * ASTR
                                       + hc + 16 * g + 8 * (m >> 1)]);
            ldsm4t(vf[2*g][0], vf[2*g][1], vf[2*g+1][0], vf[2*g+1][1], va);
        }
        #pragma unroll
        for (int mt = 0; mt < 2; ++mt)
            #pragma unroll
            for (int nt = 0; nt < 4; ++nt)
                mma16816(o[mt][nt], p[mt][kt], vf[nt]);
    }

    // ---- O overwrites Q (exclusive region per task) ----
    #pragma unroll
    for (int mt = 0; mt < 2; ++mt) {
        int r1 = rbase + 16 * mt + (lane >> 2), r2 = r1 + 8;
        #pragma unroll
        for (int nt = 0; nt < 4; ++nt) {
            int cc = hc + 8 * nt + 2 * (lane & 3);
            *(__half2*)&Qs[r1 * ASTR + cc] = __floats2half2_rn(o[mt][nt][0], o[mt][nt][1]);
            *(__half2*)&Qs[r2 * ASTR + cc] = __floats2half2_rn(o[mt][nt][2], o[mt][nt][3]);
        }
    }
}

// ---------------------------------------------------------------------------
// The fused kernel. grid(1024), 384 threads (12 warps: 4m x 3n).
// smem: Qs(128x200) Ks Vs Bs(96x200) rel(1350 f)
// ---------------------------------------------------------------------------
#define SM_Q 0
#define SM_K 25600
#define SM_V 51200
#define SM_B 76800
#define SM_R 96000
#define FUSED_SMEM (96000 * 2 + 5400)

__global__ __launch_bounds__(384, 1)
void fused_kernel(const float* __restrict__ xin, const float* __restrict__ bin,
                  const float* __restrict__ b_qkv, const float* __restrict__ b_qkv_b,
                  const float* __restrict__ rel, const float* __restrict__ b_out,
                  float* __restrict__ out)
{
    extern __shared__ __half sm[];
    __half* Qs  = sm + SM_Q;
    __half* Ks  = sm + SM_K;
    __half* Vs  = sm + SM_V;
    __half* Bsm = sm + SM_B;
    float*  rel_s = (float*)(sm + SM_R);

    const int tid = threadIdx.x, warp = tid >> 5, lane = tid & 31;
    const int m0 = blockIdx.x * 128;
    const int wm = (warp >> 2) * 32;        // 4 m-quadrants (warp/4? no: see below)
    const int wn = (warp & 3) * 32;         // placeholder; fixed below

    // 12 warps = 4m x 3n
    const int wmm = (warp / 3) * 32;
    const int wnn = (warp % 3) * 32;
    (void)wm; (void)wn;

    const __half* Wptr[8] = {
        gw_qkv + (size_t)192 * C, gw_qkv + (size_t)288 * C,
        gw_qkv + (size_t)384 * C, gw_qkv + (size_t)480 * C,
        gw_qkvb, gw_qkvb + (size_t)96 * C,
        gw_out,  gw_out  + (size_t)96 * C };

    uint4 pf[6];

    for (int i = tid; i < 1350; i += 384) rel_s[i] = rel[i];

    // ---- stage x, prefetch first weights ----
    stage_input(xin, Qs, m0, tid);
    pf_load(pf, Wptr[0], tid);
    __syncthreads();

    // ---- K, V (4 groups of 96) ----
    #pragma unroll
    for (int s = 0; s < 4; ++s) {
        pf_store(Bsm, pf, tid);
        __syncthreads();
        pf_load(pf, Wptr[s + 1], tid);          // overlaps gemm below
        float acc[2][4][4] = {};
        gemm_group(Qs, Bsm, lane, wmm, wnn, acc);
        epi_smem((s < 2) ? Ks : Vs, (s & 1) * 96,
                 b_qkv + 192 + s * 96, lane, wmm, wnn, acc);
        __syncthreads();
    }

    // ---- stage b, compute Q (fp16-parked, in-place store after sync) ----
    stage_input(bin, Qs, m0, tid);
    __syncthreads();
    {
        uint32_t parkA[16], parkB[16];
        pf_store(Bsm, pf, tid);                 // W4
        __syncthreads();
        pf_load(pf, Wptr[5], tid);
        {
            float acc[2][4][4] = {};
            gemm_group(Qs, Bsm, lane, wmm, wnn, acc);
            epi_park(parkA, b_qkv_b, lane, wnn, acc);
        }
        __syncthreads();
        pf_store(Bsm, pf, tid);                 // W5
        __syncthreads();
        pf_load(pf, Wptr[6], tid);
        {
            float acc[2][4][4] = {};
            gemm_group(Qs, Bsm, lane, wmm, wnn, acc);
            epi_park(parkB, b_qkv_b + 96, lane, wnn, acc);
        }
        __syncthreads();                        // all Qs reads done
        epi_unpark(Qs, 0,  lane, wmm, wnn, parkA);
        epi_unpark(Qs, 96, lane, wmm, wnn, parkB);
    }
    __syncthreads();

    // ---- attention: 24 tasks (2 win x 6 heads x 2 row-halves), 12 warps ----
    {
        const int gw0 = blockIdx.x * 2;
        #pragma unroll
        for (int task = warp; task < 24; task += 12) {
            int pair = task >> 1, rt = task & 1;
            int win  = (pair >= 6) ? 1 : 0;
            int head = pair - win * 6;
            int wimg = (gw0 + win) & 1023;
            attn_task32(Qs, Ks, Vs, rel_s + head * 225, win * 64, head * 32, rt,
                        (wimg >> 5) == 31, (wimg & 31) == 31, lane);
        }
    }
    __syncthreads();

    // ---- output projection + scatter ----
    int orow[2][2];
    #pragma unroll
    for (int mt = 0; mt < 2; ++mt) {
        int r0 = m0 + wmm + 16 * mt + (lane >> 2);
        orow[mt][0] = tok_to_pix_row(r0);
        orow[mt][1] = tok_to_pix_row(r0 + 8);
    }
    #pragma unroll
    for (int g = 0; g < 2; ++g) {
        pf_store(Bsm, pf, tid);                 // W6 / W7
        __syncthreads();
        if (g == 0) pf_load(pf, Wptr[7], tid);
        float acc[2][4][4] = {};
        gemm_group(Qs, Bsm, lane, wmm, wnn, acc);
        #pragma unroll
        for (int nt = 0; nt < 4; ++nt) {
            int colg = g * 96 + wnn + 8 * nt + 2 * (lane & 3);
            float b0 = b_out[colg], b1 = b_out[colg + 1];
            #pragma unroll
            for (int mt = 0; mt < 2; ++mt) {
                *(float2*)(out + orow[mt][0] + colg) =
                    make_float2(acc[mt][nt][0] + b0, acc[mt][nt][1] + b1);
                *(float2*)(out + orow[mt][1] + colg) =
                    make_float2(acc[mt][nt][2] + b0, acc[mt][nt][3] + b1);
            }
        }
        __syncthreads();
    }
}

// ---------------------------------------------------------------------------
extern "C" void kernel_launch(void* const* d_in, const int* in_sizes, int n_in,
                              void* d_out, int out_size)
{
    const float* x        = (const float*)d_in[0];
    const float* b        = (const float*)d_in[1];
    const float* w_qkv    = (const float*)d_in[2];
    const float* b_qkv    = (const float*)d_in[3];
    const float* w_qkv_b  = (const float*)d_in[4];
    const float* b_qkv_b  = (const float*)d_in[5];
    const float* rel      = (const float*)d_in[6];
    const float* w_out    = (const float*)d_in[7];
    const float* b_out    = (const float*)d_in[8];
    float* out = (float*)d_out;

    cudaFuncSetAttribute(fused_kernel, cudaFuncAttributeMaxDynamicSharedMemorySize,
                         FUSED_SMEM);

    prep_kernel<<<432, 256>>>(w_qkv, w_qkv_b, w_out);
    fused_kernel<<<1024, 384, FUSED_SMEM>>>(x, b, b_qkv, b_qkv_b, rel, b_out, out);
}